// round 16
// baseline (speedup 1.0000x reference)
#include <cuda_runtime.h>
#include <cuda_fp16.h>
#include <cstdint>

#define BD 2
#define HD 64
#define WD 64
#define CD 256
#define GD 8
#define KP 9
#define HCD 32
#define PD (HD*WD)
#define C3 (3*CD)
#define NOP 192
#define NF 768
#define MR (BD*PD)

// ---------------- scratch ----------------
__device__ float  g_qkv[MR*C3];
__device__ __half g_qh[MR*CD], g_ql[MR*CD];
__device__ float2 g_kv[MR*CD];
__device__ float  g_ompart[2*MR*NOP];    // split-K partial sums (no bias)
__device__ float  g_combB[NOP];
__device__ __half g_xhi[MR*CD], g_xlo[MR*CD];
__device__ __half g_qwh[C3*CD], g_qwl[C3*CD];
__device__ __half g_pwh[CD*CD], g_pwl[CD*CD];
__device__ __half g_cwh[NOP*NF], g_cwl[NOP*NF];
__device__ __half g_aoh[MR*CD], g_aol[MR*CD];

__constant__ float c_PTS[18] = {-1,-1,-1,0,-1,1,0,-1,0,0,0,1,1,-1,1,0,1,1};

// ---------------- helpers ----------------
__device__ __forceinline__ uint32_t smem_u32(const void* p) {
    uint32_t a;
    asm("{ .reg .u64 t; cvta.to.shared.u64 t, %1; cvt.u32.u64 %0, t; }" : "=r"(a) : "l"(p));
    return a;
}
__device__ __forceinline__ void cp16(uint32_t dst, const void* src) {
    asm volatile("cp.async.cg.shared.global [%0], [%1], 16;" :: "r"(dst), "l"(src));
}
#define CP_COMMIT() asm volatile("cp.async.commit_group;" ::: "memory")
#define CP_WAIT0()  asm volatile("cp.async.wait_group 0;" ::: "memory")
#define CP_WAIT1()  asm volatile("cp.async.wait_group 1;" ::: "memory")
#define LDSM_X4(r, a) asm volatile( \
    "ldmatrix.sync.aligned.m8n8.x4.shared.b16 {%0,%1,%2,%3}, [%4];" \
    : "=r"((r)[0]),"=r"((r)[1]),"=r"((r)[2]),"=r"((r)[3]) : "r"(a))
#define MMA16816(c, a, b) asm volatile( \
    "mma.sync.aligned.m16n8k16.row.col.f32.f16.f16.f32 " \
    "{%0,%1,%2,%3}, {%4,%5,%6,%7}, {%8,%9}, {%0,%1,%2,%3};" \
    : "+f"((c)[0]),"+f"((c)[1]),"+f"((c)[2]),"+f"((c)[3]) \
    : "r"((a)[0]),"r"((a)[1]),"r"((a)[2]),"r"((a)[3]), "r"((b)[0]),"r"((b)[1]))

__device__ __forceinline__ void split1(float v, __half& hi, __half& lo) {
    hi = __float2half_rn(v);
    lo = __float2half_rn(v - __half2float(hi));
}

// ====== split-fp16 GEMM: 64x64 tiles, 128 threads, 3-stage pipeline ======
#define GT 2560
#define GEMM_SMEM (4 * 3 * GT * 2)      // 61440

__global__ void __launch_bounds__(128, 3) gemm_kernel(
    const __half* __restrict__ Ah, const __half* __restrict__ Al,
    const __half* __restrict__ Bh, const __half* __restrict__ Bl,
    const float* __restrict__ bias, float* __restrict__ C, int N, int K, int n3)
{
    extern __shared__ __half sm[];
    __half* sAh = sm;
    __half* sAl = sAh + 3*GT;
    __half* sBh = sAl + 3*GT;
    __half* sBl = sBh + 3*GT;

    int tid = threadIdx.x;
    int warp = tid >> 5, lane = tid & 31;
    int wm = warp >> 1, wn = warp & 1;
    int row0 = blockIdx.y * 64, col0 = blockIdx.x * 64;
    bool full3 = (col0 < n3);

    float acc[2][4][4];
#pragma unroll
    for (int mi = 0; mi < 2; mi++)
#pragma unroll
        for (int j = 0; j < 4; j++)
#pragma unroll
            for (int r = 0; r < 4; r++) acc[mi][j][r] = 0.f;

#define STAGE(kc, s) do { \
    int k0 = (kc) << 5; \
    _Pragma("unroll") \
    for (int i = 0; i < 2; i++) { \
        int e = tid + i * 128; \
        int r = e >> 2, cs = (e & 3) * 8; \
        size_t ga = (size_t)(row0 + r) * K + k0 + cs; \
        cp16(smem_u32(&sAh[(s)*GT + r*40 + cs]), Ah + ga); \
        if (full3) cp16(smem_u32(&sAl[(s)*GT + r*40 + cs]), Al + ga); \
        size_t gb = (size_t)(col0 + r) * K + k0 + cs; \
        cp16(smem_u32(&sBh[(s)*GT + r*40 + cs]), Bh + gb); \
        cp16(smem_u32(&sBl[(s)*GT + r*40 + cs]), Bl + gb); \
    } \
} while (0)

    int nk = K >> 5;
    STAGE(0, 0); CP_COMMIT();
    if (nk > 1) { STAGE(1, 1); CP_COMMIT(); }

    int cur = 0, nxt2 = 2;
    for (int kc = 0; kc < nk; kc++) {
        if (kc + 1 < nk) CP_WAIT1(); else CP_WAIT0();
        __syncthreads();
        if (kc + 2 < nk) {
            STAGE(kc + 2, nxt2);
            CP_COMMIT();
            nxt2 = (nxt2 == 2) ? 0 : nxt2 + 1;
        }
#pragma unroll
        for (int ks = 0; ks < 2; ks++) {
            uint32_t aH[2][4], aL[2][4], bH[4][2], bL[4][2];
#pragma unroll
            for (int mi = 0; mi < 2; mi++) {
                int rowa = wm * 32 + mi * 16 + (lane & 15);
                int cola = ks * 16 + (lane >> 4) * 8;
                LDSM_X4(aH[mi], smem_u32(&sAh[cur*GT + rowa*40 + cola]));
                if (full3)
                    LDSM_X4(aL[mi], smem_u32(&sAl[cur*GT + rowa*40 + cola]));
            }
#pragma unroll
            for (int jp = 0; jp < 2; jp++) {
                int rowb = wn * 32 + jp * 16 + ((lane >> 4) & 1) * 8 + (lane & 7);
                int colb = ks * 16 + ((lane >> 3) & 1) * 8;
                uint32_t t4[4];
                LDSM_X4(t4, smem_u32(&sBh[cur*GT + rowb*40 + colb]));
                bH[jp*2][0] = t4[0]; bH[jp*2][1] = t4[1];
                bH[jp*2+1][0] = t4[2]; bH[jp*2+1][1] = t4[3];
                LDSM_X4(t4, smem_u32(&sBl[cur*GT + rowb*40 + colb]));
                bL[jp*2][0] = t4[0]; bL[jp*2][1] = t4[1];
                bL[jp*2+1][0] = t4[2]; bL[jp*2+1][1] = t4[3];
            }
#pragma unroll
            for (int mi = 0; mi < 2; mi++)
#pragma unroll
                for (int j = 0; j < 4; j++) {
                    MMA16816(acc[mi][j], aH[mi], bH[j]);
                    MMA16816(acc[mi][j], aH[mi], bL[j]);
                }
            if (full3) {
#pragma unroll
                for (int mi = 0; mi < 2; mi++)
#pragma unroll
                    for (int j = 0; j < 4; j++)
                        MMA16816(acc[mi][j], aL[mi], bH[j]);
            }
        }
        cur = (cur == 2) ? 0 : cur + 1;
    }
#undef STAGE

    int g = lane >> 2, t = lane & 3;
#pragma unroll
    for (int mi = 0; mi < 2; mi++)
#pragma unroll
        for (int j = 0; j < 4; j++) {
            int col = col0 + wn * 32 + j * 8 + t * 2;
            float2 bv = *reinterpret_cast<const float2*>(&bias[col]);
            int r0 = row0 + wm * 32 + mi * 16 + g;
            float2 o0 = make_float2(acc[mi][j][0] + bv.x, acc[mi][j][1] + bv.y);
            float2 o1 = make_float2(acc[mi][j][2] + bv.x, acc[mi][j][3] + bv.y);
            *reinterpret_cast<float2*>(&C[(size_t)r0 * N + col]) = o0;
            *reinterpret_cast<float2*>(&C[(size_t)(r0 + 8) * N + col]) = o1;
        }
}

// ====== fused offset/mask GEMM: split-K=2, 64x64 tiles, 128 threads ======
// grid (3, 128, 2); z half accumulates chunks [z*12, z*12+12) -> g_ompart[z].
#define OAT 2560
#define OBT 2560
#define OM_SMEM ((2*OAT*2 + 2*OBT*2) * 2)   // 40960 bytes

__device__ __forceinline__ void om_gather(
    int kc, int b, int h, int tid, uint2* hv, uint2* lv)
{
    int f0 = kc << 5;
    int dy, dx, cofs;
    if (f0 < 576) { int t = f0 >> 6; dy = t / 3 - 1; dx = t % 3 - 1; cofs = f0 & 63; }
    else          { dy = 0; dx = 0; cofs = 64 + (f0 - 576); }
    int hh = h + dy;
    bool rowok = (hh >= 0 && hh < HD);
    const __half* rh = g_qh + ((size_t)(b * HD + hh) * WD) * CD + cofs;
    const __half* rl = g_ql + ((size_t)(b * HD + hh) * WD) * CD + cofs;
#pragma unroll
    for (int i = 0; i < 4; i++) {
        int idx = tid + i * 128;
        int px = idx >> 3;
        int c4 = (idx & 7) << 2;
        int xx = px + dx;
        hv[i] = make_uint2(0u, 0u); lv[i] = make_uint2(0u, 0u);
        if (rowok && xx >= 0 && xx < WD) {
            size_t base = (size_t)xx * CD + c4;
            hv[i] = *reinterpret_cast<const uint2*>(rh + base);
            lv[i] = *reinterpret_cast<const uint2*>(rl + base);
        }
    }
}

__global__ void __launch_bounds__(128, 4) offmask_gemm_kernel()
{
    extern __shared__ __half sm[];
    __half* sAh = sm;
    __half* sAl = sAh + 2*OAT;
    __half* sBh = sAl + 2*OAT;
    __half* sBl = sBh + 2*OBT;

    int tid = threadIdx.x;
    int warp = tid >> 5, lane = tid & 31;
    int wm = warp >> 1, wn = warp & 1;
    int row0 = blockIdx.y * 64, col0 = blockIdx.x * 64;
    int z = blockIdx.z;
    int b = row0 >> 12;
    int h = (row0 & 4095) >> 6;
    const int KC0 = z * 12, KC1 = KC0 + 12;

    float acc[2][4][4];
#pragma unroll
    for (int mi = 0; mi < 2; mi++)
#pragma unroll
        for (int j = 0; j < 4; j++)
#pragma unroll
            for (int r = 0; r < 4; r++) acc[mi][j][r] = 0.f;

#define OM_STS(s) do { \
    _Pragma("unroll") \
    for (int i = 0; i < 4; i++) { \
        int idx = tid + i * 128; \
        int px = idx >> 3, c4 = (idx & 7) << 2; \
        *reinterpret_cast<uint2*>(&sAh[(s)*OAT + px*40 + c4]) = hv[i]; \
        *reinterpret_cast<uint2*>(&sAl[(s)*OAT + px*40 + c4]) = lv[i]; \
    } \
} while (0)
#define OM_CPB(kc, s) do { \
    _Pragma("unroll") \
    for (int i = 0; i < 2; i++) { \
        int e = tid + i * 128; \
        int r = e >> 2, cs = (e & 3) * 8; \
        size_t gb = (size_t)(col0 + r) * NF + ((kc) << 5) + cs; \
        cp16(smem_u32(&sBh[(s)*OBT + r*40 + cs]), g_cwh + gb); \
        cp16(smem_u32(&sBl[(s)*OBT + r*40 + cs]), g_cwl + gb); \
    } \
} while (0)

    uint2 hv[4], lv[4];
    om_gather(KC0, b, h, tid, hv, lv);
    OM_STS(0);
    OM_CPB(KC0, 0);
    CP_COMMIT();
    om_gather(KC0 + 1, b, h, tid, hv, lv);

    for (int kc = KC0; kc < KC1; kc++) {
        int cur = (kc - KC0) & 1;
        CP_WAIT0();
        __syncthreads();
        if (kc + 1 < KC1) {
            OM_STS(cur ^ 1);
            OM_CPB(kc + 1, cur ^ 1);
            CP_COMMIT();
        }
        if (kc + 2 < KC1)
            om_gather(kc + 2, b, h, tid, hv, lv);

#pragma unroll
        for (int ks = 0; ks < 2; ks++) {
            uint32_t aH[2][4], aL[2][4], bH[4][2], bL[4][2];
#pragma unroll
            for (int mi = 0; mi < 2; mi++) {
                int rowa = wm * 32 + mi * 16 + (lane & 15);
                int cola = ks * 16 + (lane >> 4) * 8;
                LDSM_X4(aH[mi], smem_u32(&sAh[cur*OAT + rowa*40 + cola]));
                LDSM_X4(aL[mi], smem_u32(&sAl[cur*OAT + rowa*40 + cola]));
            }
#pragma unroll
            for (int jp = 0; jp < 2; jp++) {
                int rowb = wn * 32 + jp * 16 + ((lane >> 4) & 1) * 8 + (lane & 7);
                int colb = ks * 16 + ((lane >> 3) & 1) * 8;
                uint32_t t4[4];
                LDSM_X4(t4, smem_u32(&sBh[cur*OBT + rowb*40 + colb]));
                bH[jp*2][0] = t4[0]; bH[jp*2][1] = t4[1];
                bH[jp*2+1][0] = t4[2]; bH[jp*2+1][1] = t4[3];
                LDSM_X4(t4, smem_u32(&sBl[cur*OBT + rowb*40 + colb]));
                bL[jp*2][0] = t4[0]; bL[jp*2][1] = t4[1];
                bL[jp*2+1][0] = t4[2]; bL[jp*2+1][1] = t4[3];
            }
#pragma unroll
            for (int mi = 0; mi < 2; mi++)
#pragma unroll
                for (int j = 0; j < 4; j++) {
                    MMA16816(acc[mi][j], aH[mi], bH[j]);
                    MMA16816(acc[mi][j], aH[mi], bL[j]);
                    MMA16816(acc[mi][j], aL[mi], bH[j]);
                }
        }
    }
#undef OM_STS
#undef OM_CPB

    float* outp = g_ompart + (size_t)z * MR * NOP;
    int g = lane >> 2, t = lane & 3;
#pragma unroll
    for (int mi = 0; mi < 2; mi++)
#pragma unroll
        for (int j = 0; j < 4; j++) {
            int col = col0 + wn * 32 + j * 8 + t * 2;
            int r0 = row0 + wm * 32 + mi * 16 + g;
            float2 o0 = make_float2(acc[mi][j][0], acc[mi][j][1]);
            float2 o1 = make_float2(acc[mi][j][2], acc[mi][j][3]);
            *reinterpret_cast<float2*>(&outp[(size_t)r0 * NOP + col]) = o0;
            *reinterpret_cast<float2*>(&outp[(size_t)(r0 + 8) * NOP + col]) = o1;
        }
}

// ------- merged prep -------
__global__ void __launch_bounds__(256) allprep_kernel(
    const float* __restrict__ x, const float* __restrict__ qkv_w,
    const float* __restrict__ proj_w,
    const float* __restrict__ off_pconv_w, const float* __restrict__ off_w,
    const float* __restrict__ off_b, const float* __restrict__ mask_pconv_w,
    const float* __restrict__ mask_w, const float* __restrict__ mask_b)
{
    int bid = blockIdx.x, tid = threadIdx.x;
    if (bid < NOP * 3) {
        int o = bid / 3;
        int f = (bid % 3) * 256 + tid;
        if (o >= 153) {
            g_cwh[(size_t)o * NF + f] = __float2half_rn(0.f);
            g_cwl[(size_t)o * NF + f] = __float2half_rn(0.f);
            if (tid == 0 && (bid % 3) == 0) g_combB[o] = 0.f;
            return;
        }
        bool is_mask = (o >= 144);
        int g = 0, j = 0, kk = 0;
        if (!is_mask) { g = o / 18; j = o % 18; } else { kk = o - 144; }
        float s;
        if (f < 576) {
            int t = f >> 6, ic = f & 63;
            s = 0.f;
            if (!is_mask) {
                const float* ow = off_w + (g * 18 + j) * 256;
                const float* pc = off_pconv_w + ((size_t)(g * 64) * 64 + ic) * 9 + t;
#pragma unroll 4
                for (int oc = 0; oc < 64; oc++) s += ow[oc] * pc[(size_t)oc * 64 * 9];
            } else {
                const float* mw = mask_w + kk * 256;
                const float* pc = mask_pconv_w + (size_t)ic * 9 + t;
#pragma unroll 4
                for (int oc = 0; oc < 64; oc++) s += mw[oc] * pc[(size_t)oc * 64 * 9];
            }
        } else {
            int ch = f - 512;
            s = is_mask ? mask_w[kk * 256 + ch] : off_w[(g * 18 + j) * 256 + ch];
        }
        __half h, l; split1(s, h, l);
        g_cwh[(size_t)o * NF + f] = h;
        g_cwl[(size_t)o * NF + f] = l;
        if (tid == 0 && (bid % 3) == 0)
            g_combB[o] = is_mask ? mask_b[kk]
                                 : (off_b[g * 18 + j] + c_PTS[j] * (float)(2 * g + 1));
    } else if (bid < NOP * 3 + C3 + CD) {
        int wb = bid - NOP * 3;
        if (wb < C3) {
            __half h, l; split1(qkv_w[(size_t)tid * C3 + wb], h, l);
            g_qwh[(size_t)wb * CD + tid] = h;
            g_qwl[(size_t)wb * CD + tid] = l;
        } else {
            int o = wb - C3;
            __half h, l; split1(proj_w[(size_t)tid * CD + o], h, l);
            g_pwh[(size_t)o * CD + tid] = h;
            g_pwl[(size_t)o * CD + tid] = l;
        }
    } else {
        int xb = bid - (NOP * 3 + C3 + CD);
        int i = (xb * 256 + tid) * 4;
        float4 v = *reinterpret_cast<const float4*>(&x[i]);
        float f[4] = {v.x, v.y, v.z, v.w};
#pragma unroll
        for (int j = 0; j < 4; j++) {
            __half h, l; split1(f[j], h, l);
            g_xhi[i + j] = h; g_xlo[i + j] = l;
        }
    }
}

// ---------------- depthwise 3x3 ----------------
__global__ void __launch_bounds__(192) dwconv_kernel(
    const float* __restrict__ in, const float* __restrict__ w,
    const float* __restrict__ bias)
{
    int c = threadIdx.x * 4;
    int x0 = blockIdx.x * 4, y = blockIdx.y, b = blockIdx.z;
    float4 bz = *reinterpret_cast<const float4*>(&bias[c]);
    float4 acc[4] = {bz, bz, bz, bz};
#pragma unroll
    for (int ky = 0; ky < 3; ky++) {
        int yy = y + ky - 1;
        if (yy < 0 || yy >= HD) continue;
        const float* rowp = in + ((size_t)(b * HD + yy) * WD) * C3 + c;
        float4 iv[6];
#pragma unroll
        for (int j = 0; j < 6; j++) {
            int xx = x0 - 1 + j;
            iv[j] = (xx >= 0 && xx < WD)
                ? *reinterpret_cast<const float4*>(rowp + (size_t)xx * C3)
                : make_float4(0.f, 0.f, 0.f, 0.f);
        }
#pragma unroll
        for (int kx = 0; kx < 3; kx++) {
            float4 wv = *reinterpret_cast<const float4*>(&w[(ky * 3 + kx) * C3 + c]);
#pragma unroll
            for (int p = 0; p < 4; p++) {
                acc[p].x += wv.x * iv[p + kx].x; acc[p].y += wv.y * iv[p + kx].y;
                acc[p].z += wv.z * iv[p + kx].z; acc[p].w += wv.w * iv[p + kx].w;
            }
        }
    }
#pragma unroll
    for (int p = 0; p < 4; p++) {
        size_t pix = (size_t)(b * HD + y) * WD + x0 + p;
        if (c < CD) {
            __half h0,h1,h2,h3,l0,l1,l2,l3;
            split1(acc[p].x,h0,l0); split1(acc[p].y,h1,l1);
            split1(acc[p].z,h2,l2); split1(acc[p].w,h3,l3);
            size_t o = pix * CD + c;
            *reinterpret_cast<__half2*>(&g_qh[o])   = __halves2half2(h0,h1);
            *reinterpret_cast<__half2*>(&g_qh[o+2]) = __halves2half2(h2,h3);
            *reinterpret_cast<__half2*>(&g_ql[o])   = __halves2half2(l0,l1);
            *reinterpret_cast<__half2*>(&g_ql[o+2]) = __halves2half2(l2,l3);
        } else if (c < 2 * CD) {
            float2* bp = &g_kv[pix * CD + (c - CD)];
            bp[0].x = acc[p].x; bp[1].x = acc[p].y;
            bp[2].x = acc[p].z; bp[3].x = acc[p].w;
        } else {
            float2* bp = &g_kv[pix * CD + (c - 2 * CD)];
            bp[0].y = acc[p].x; bp[1].y = acc[p].y;
            bp[2].y = acc[p].z; bp[3].y = acc[p].w;
        }
    }
}

// ---------------- deformable attention (adds split-K partials + bias) ------
__global__ void __launch_bounds__(256) attn_kernel()
{
    int warp = threadIdx.x >> 5, lane = threadIdx.x & 31;
    int px = blockIdx.x * 8 + warp;
    int g = blockIdx.y, b = blockIdx.z;
    int h = px >> 6, w = px & 63;

    size_t pix = (size_t)(b * HD + h) * WD + w;
    const float* om0 = g_ompart + pix * NOP;
    const float* om1 = g_ompart + (size_t)MR * NOP + pix * NOP;
    size_t qi = pix * CD + g * HCD + lane;
    float qv = (__half2float(g_qh[qi]) + __half2float(g_ql[qi]))
             * 0.17677669529663687f;

    float attn[KP], vk[KP];
#pragma unroll
    for (int k = 0; k < KP; k++) {
        int io = g * 18 + 2 * k;
        float ox = om0[io] + om1[io] + g_combB[io];
        float oy = om0[io + 1] + om1[io + 1] + g_combB[io + 1];
        float mk = om0[144 + k] + om1[144 + k] + g_combB[144 + k];
        float cx = fminf(fmaxf((float)w + ox, 0.f), (float)(WD - 1));
        float cy = fminf(fmaxf((float)h + oy, 0.f), (float)(HD - 1));
        float x0f = floorf(cx), y0f = floorf(cy);
        float fx = cx - x0f, fy = cy - y0f;
        int x0 = (int)x0f, y0 = (int)y0f;
        int x1 = min(x0 + 1, WD - 1), y1 = min(y0 + 1, HD - 1);
        size_t i00 = ((size_t)(b * HD + y0) * WD + x0) * CD + g * HCD + lane;
        size_t i01 = ((size_t)(b * HD + y0) * WD + x1) * CD + g * HCD + lane;
        size_t i10 = ((size_t)(b * HD + y1) * WD + x0) * CD + g * HCD + lane;
        size_t i11 = ((size_t)(b * HD + y1) * WD + x1) * CD + g * HCD + lane;
        float2 kv00 = g_kv[i00], kv01 = g_kv[i01];
        float2 kv10 = g_kv[i10], kv11 = g_kv[i11];
        float w00 = (1.f - fx) * (1.f - fy), w01 = fx * (1.f - fy);
        float w10 = (1.f - fx) * fy,         w11 = fx * fy;
        float kvv = kv00.x*w00 + kv01.x*w01 + kv10.x*w10 + kv11.x*w11;
        float vvv = kv00.y*w00 + kv01.y*w01 + kv10.y*w10 + kv11.y*w11;
        kvv *= mk; vvv *= mk;
        float d = qv * kvv;
#pragma unroll
        for (int s = 16; s; s >>= 1) d += __shfl_xor_sync(0xffffffffu, d, s);
        attn[k] = d;
        vk[k] = vvv;
    }
    float m = attn[0];
#pragma unroll
    for (int k = 1; k < KP; k++) m = fmaxf(m, attn[k]);
    float ssum = 0.f, o = 0.f;
#pragma unroll
    for (int k = 0; k < KP; k++) {
        float e = __expf(attn[k] - m);
        ssum += e;
        o += e * vk[k];
    }
    o /= ssum;
    size_t oi = pix * CD + g * HCD + lane;
    __half hh, ll; split1(o, hh, ll);
    g_aoh[oi] = hh; g_aol[oi] = ll;
}

// --------------------------------- launch ---------------------------------
extern "C" void kernel_launch(void* const* d_in, const int* in_sizes, int n_in,
                              void* d_out, int out_size)
{
    const float* x            = (const float*)d_in[0];
    const float* qkv_w        = (const float*)d_in[1];
    const float* qkv_b        = (const float*)d_in[2];
    const float* dw_w         = (const float*)d_in[3];
    const float* dw_b         = (const float*)d_in[4];
    const float* off_pconv_w  = (const float*)d_in[5];
    const float* off_w        = (const float*)d_in[6];
    const float* off_b        = (const float*)d_in[7];
    const float* mask_pconv_w = (const float*)d_in[8];
    const float* mask_w       = (const float*)d_in[9];
    const float* mask_b       = (const float*)d_in[10];
    const float* proj_w       = (const float*)d_in[11];
    const float* proj_b       = (const float*)d_in[12];
    float* out = (float*)d_out;

    cudaFuncSetAttribute(gemm_kernel,
                         cudaFuncAttributeMaxDynamicSharedMemorySize, GEMM_SMEM);
    cudaFuncSetAttribute(offmask_gemm_kernel,
                         cudaFuncAttributeMaxDynamicSharedMemorySize, OM_SMEM);

    __half *xh, *xl, *qwh, *qwl, *pwh, *pwl, *aoh, *aol;
    float *qkv;
    cudaGetSymbolAddress((void**)&xh, g_xhi);   cudaGetSymbolAddress((void**)&xl, g_xlo);
    cudaGetSymbolAddress((void**)&qwh, g_qwh);  cudaGetSymbolAddress((void**)&qwl, g_qwl);
    cudaGetSymbolAddress((void**)&pwh, g_pwh);  cudaGetSymbolAddress((void**)&pwl, g_pwl);
    cudaGetSymbolAddress((void**)&aoh, g_aoh);  cudaGetSymbolAddress((void**)&aol, g_aol);
    cudaGetSymbolAddress((void**)&qkv, g_qkv);

    allprep_kernel<<<NOP * 3 + C3 + CD + 2048, 256>>>(
        x, qkv_w, proj_w, off_pconv_w, off_w, off_b,
        mask_pconv_w, mask_w, mask_b);
    {
        dim3 grid(C3 / 64, MR / 64);
        gemm_kernel<<<grid, 128, GEMM_SMEM>>>(xh, xl, qwh, qwl, qkv_b, qkv,
                                              C3, CD, CD);
    }
    {
        dim3 grid(WD / 4, HD, BD);
        dwconv_kernel<<<grid, 192>>>(qkv, dw_w, dw_b);
    }
    {
        dim3 grid(NOP / 64, MR / 64, 2);
        offmask_gemm_kernel<<<grid, 128, OM_SMEM>>>();     // profiled slot
    }
    {
        dim3 grid(PD / 8, GD, BD);
        attn_kernel<<<grid, 256>>>();
    }
    {
        dim3 grid(CD / 64, MR / 64);
        gemm_kernel<<<grid, 128, GEMM_SMEM>>>(aoh, aol, pwh, pwl, proj_b, out,
                                              CD, CD, 0);
    }
}

// round 17
// speedup vs baseline: 1.0698x; 1.0698x over previous
#include <cuda_runtime.h>
#include <cuda_fp16.h>
#include <cstdint>

#define BD 2
#define HD 64
#define WD 64
#define CD 256
#define GD 8
#define KP 9
#define HCD 32
#define PD (HD*WD)
#define C3 (3*CD)
#define NOP 192
#define NF 768
#define MR (BD*PD)

// ---------------- scratch ----------------
__device__ float  g_qkv[MR*C3];
__device__ __half g_qh[MR*CD], g_ql[MR*CD];
__device__ float2 g_kv[MR*CD];
__device__ float  g_offmask[MR*NOP];
__device__ float  g_combB[NOP];
__device__ __half g_xhi[MR*CD], g_xlo[MR*CD];
__device__ __half g_qwh[C3*CD], g_qwl[C3*CD];
__device__ __half g_pwh[CD*CD], g_pwl[CD*CD];
__device__ __half g_cwh[NOP*NF], g_cwl[NOP*NF];
__device__ __half g_aoh[MR*CD], g_aol[MR*CD];

__constant__ float c_PTS[18] = {-1,-1,-1,0,-1,1,0,-1,0,0,0,1,1,-1,1,0,1,1};

// ---------------- helpers ----------------
__device__ __forceinline__ uint32_t smem_u32(const void* p) {
    uint32_t a;
    asm("{ .reg .u64 t; cvta.to.shared.u64 t, %1; cvt.u32.u64 %0, t; }" : "=r"(a) : "l"(p));
    return a;
}
__device__ __forceinline__ void cp16(uint32_t dst, const void* src) {
    asm volatile("cp.async.cg.shared.global [%0], [%1], 16;" :: "r"(dst), "l"(src));
}
#define CP_COMMIT() asm volatile("cp.async.commit_group;" ::: "memory")
#define CP_WAIT0()  asm volatile("cp.async.wait_group 0;" ::: "memory")
#define CP_WAIT1()  asm volatile("cp.async.wait_group 1;" ::: "memory")
#define LDSM_X4(r, a) asm volatile( \
    "ldmatrix.sync.aligned.m8n8.x4.shared.b16 {%0,%1,%2,%3}, [%4];" \
    : "=r"((r)[0]),"=r"((r)[1]),"=r"((r)[2]),"=r"((r)[3]) : "r"(a))
#define MMA16816(c, a, b) asm volatile( \
    "mma.sync.aligned.m16n8k16.row.col.f32.f16.f16.f32 " \
    "{%0,%1,%2,%3}, {%4,%5,%6,%7}, {%8,%9}, {%0,%1,%2,%3};" \
    : "+f"((c)[0]),"+f"((c)[1]),"+f"((c)[2]),"+f"((c)[3]) \
    : "r"((a)[0]),"r"((a)[1]),"r"((a)[2]),"r"((a)[3]), "r"((b)[0]),"r"((b)[1]))

__device__ __forceinline__ void split1(float v, __half& hi, __half& lo) {
    hi = __float2half_rn(v);
    lo = __float2half_rn(v - __half2float(hi));
}

// ====== split-fp16 GEMM: 128x64 tiles, 256 thr, 3-stage (R14 champion) =====
#define AT 5120
#define BT 2560
#define GEMM_SMEM ((3*AT*2 + 3*BT*2) * 2)   // 92160

__global__ void __launch_bounds__(256, 2) gemm_kernel(
    const __half* __restrict__ Ah, const __half* __restrict__ Al,
    const __half* __restrict__ Bh, const __half* __restrict__ Bl,
    const float* __restrict__ bias, float* __restrict__ C, int N, int K, int n3)
{
    extern __shared__ __half sm[];
    __half* sAh = sm;
    __half* sAl = sAh + 3*AT;
    __half* sBh = sAl + 3*AT;
    __half* sBl = sBh + 3*BT;

    int tid = threadIdx.x;
    int warp = tid >> 5, lane = tid & 31;
    int wm = warp >> 1, wn = warp & 1;
    int row0 = blockIdx.y * 128, col0 = blockIdx.x * 64;
    bool full3 = (col0 < n3);

    float acc[2][4][4];
#pragma unroll
    for (int mi = 0; mi < 2; mi++)
#pragma unroll
        for (int j = 0; j < 4; j++)
#pragma unroll
            for (int r = 0; r < 4; r++) acc[mi][j][r] = 0.f;

#define STAGE(kc, s) do { \
    int k0 = (kc) << 5; \
    _Pragma("unroll") \
    for (int i = 0; i < 2; i++) { \
        int e = tid + i * 256; \
        int r = e >> 2, cs = (e & 3) * 8; \
        size_t ga = (size_t)(row0 + r) * K + k0 + cs; \
        cp16(smem_u32(&sAh[(s)*AT + r*40 + cs]), Ah + ga); \
        if (full3) cp16(smem_u32(&sAl[(s)*AT + r*40 + cs]), Al + ga); \
    } \
    { int r = tid >> 2, cs = (tid & 3) * 8; \
      size_t gb = (size_t)(col0 + r) * K + k0 + cs; \
      cp16(smem_u32(&sBh[(s)*BT + r*40 + cs]), Bh + gb); \
      cp16(smem_u32(&sBl[(s)*BT + r*40 + cs]), Bl + gb); } \
} while (0)

    int nk = K >> 5;
    STAGE(0, 0); CP_COMMIT();
    if (nk > 1) { STAGE(1, 1); CP_COMMIT(); }

    int cur = 0, nxt2 = 2;
    for (int kc = 0; kc < nk; kc++) {
        if (kc + 1 < nk) CP_WAIT1(); else CP_WAIT0();
        __syncthreads();
        if (kc + 2 < nk) {
            STAGE(kc + 2, nxt2);
            CP_COMMIT();
            nxt2 = (nxt2 == 2) ? 0 : nxt2 + 1;
        }
        uint32_t aH[2][2][4], aL[2][2][4], bH[2][4][2], bL[2][4][2];
#pragma unroll
        for (int ks = 0; ks < 2; ks++) {
#pragma unroll
            for (int mi = 0; mi < 2; mi++) {
                int rowa = wm * 32 + mi * 16 + (lane & 15);
                int cola = ks * 16 + (lane >> 4) * 8;
                LDSM_X4(aH[ks][mi], smem_u32(&sAh[cur*AT + rowa*40 + cola]));
                if (full3)
                    LDSM_X4(aL[ks][mi], smem_u32(&sAl[cur*AT + rowa*40 + cola]));
            }
#pragma unroll
            for (int jp = 0; jp < 2; jp++) {
                int rowb = wn * 32 + jp * 16 + ((lane >> 4) & 1) * 8 + (lane & 7);
                int colb = ks * 16 + ((lane >> 3) & 1) * 8;
                uint32_t t4[4];
                LDSM_X4(t4, smem_u32(&sBh[cur*BT + rowb*40 + colb]));
                bH[ks][jp*2][0] = t4[0]; bH[ks][jp*2][1] = t4[1];
                bH[ks][jp*2+1][0] = t4[2]; bH[ks][jp*2+1][1] = t4[3];
                LDSM_X4(t4, smem_u32(&sBl[cur*BT + rowb*40 + colb]));
                bL[ks][jp*2][0] = t4[0]; bL[ks][jp*2][1] = t4[1];
                bL[ks][jp*2+1][0] = t4[2]; bL[ks][jp*2+1][1] = t4[3];
            }
        }
#pragma unroll
        for (int ks = 0; ks < 2; ks++) {
#pragma unroll
            for (int mi = 0; mi < 2; mi++)
#pragma unroll
                for (int j = 0; j < 4; j++) {
                    MMA16816(acc[mi][j], aH[ks][mi], bH[ks][j]);
                    MMA16816(acc[mi][j], aH[ks][mi], bL[ks][j]);
                }
            if (full3) {
#pragma unroll
                for (int mi = 0; mi < 2; mi++)
#pragma unroll
                    for (int j = 0; j < 4; j++)
                        MMA16816(acc[mi][j], aL[ks][mi], bH[ks][j]);
            }
        }
        cur = (cur == 2) ? 0 : cur + 1;
    }
#undef STAGE

    int g = lane >> 2, t = lane & 3;
#pragma unroll
    for (int mi = 0; mi < 2; mi++)
#pragma unroll
        for (int j = 0; j < 4; j++) {
            int col = col0 + wn * 32 + j * 8 + t * 2;
            float2 bv = *reinterpret_cast<const float2*>(&bias[col]);
            int r0 = row0 + wm * 32 + mi * 16 + g;
            float2 o0 = make_float2(acc[mi][j][0] + bv.x, acc[mi][j][1] + bv.y);
            float2 o1 = make_float2(acc[mi][j][2] + bv.x, acc[mi][j][3] + bv.y);
            *reinterpret_cast<float2*>(&C[(size_t)r0 * N + col]) = o0;
            *reinterpret_cast<float2*>(&C[(size_t)(r0 + 8) * N + col]) = o1;
        }
}

// ====== fused offset/mask GEMM: 64x64 tiles, 128 threads (R14 champion) ====
#define OAT 2560
#define OBT 2560
#define OM_SMEM ((2*OAT*2 + 2*OBT*2) * 2)   // 40960

__device__ __forceinline__ void om_gather(
    int kc, int b, int h, int tid, uint2* hv, uint2* lv)
{
    int f0 = kc << 5;
    int dy, dx, cofs;
    if (f0 < 576) { int t = f0 >> 6; dy = t / 3 - 1; dx = t % 3 - 1; cofs = f0 & 63; }
    else          { dy = 0; dx = 0; cofs = 64 + (f0 - 576); }
    int hh = h + dy;
    bool rowok = (hh >= 0 && hh < HD);
    const __half* rh = g_qh + ((size_t)(b * HD + hh) * WD) * CD + cofs;
    const __half* rl = g_ql + ((size_t)(b * HD + hh) * WD) * CD + cofs;
#pragma unroll
    for (int i = 0; i < 4; i++) {
        int idx = tid + i * 128;
        int px = idx >> 3;
        int c4 = (idx & 7) << 2;
        int xx = px + dx;
        hv[i] = make_uint2(0u, 0u); lv[i] = make_uint2(0u, 0u);
        if (rowok && xx >= 0 && xx < WD) {
            size_t base = (size_t)xx * CD + c4;
            hv[i] = *reinterpret_cast<const uint2*>(rh + base);
            lv[i] = *reinterpret_cast<const uint2*>(rl + base);
        }
    }
}

__global__ void __launch_bounds__(128, 4) offmask_gemm_kernel()
{
    extern __shared__ __half sm[];
    __half* sAh = sm;
    __half* sAl = sAh + 2*OAT;
    __half* sBh = sAl + 2*OAT;
    __half* sBl = sBh + 2*OBT;

    int tid = threadIdx.x;
    int warp = tid >> 5, lane = tid & 31;
    int wm = warp >> 1, wn = warp & 1;
    int row0 = blockIdx.y * 64, col0 = blockIdx.x * 64;
    int b = row0 >> 12;
    int h = (row0 & 4095) >> 6;

    float acc[2][4][4];
#pragma unroll
    for (int mi = 0; mi < 2; mi++)
#pragma unroll
        for (int j = 0; j < 4; j++)
#pragma unroll
            for (int r = 0; r < 4; r++) acc[mi][j][r] = 0.f;

#define OM_STS(s) do { \
    _Pragma("unroll") \
    for (int i = 0; i < 4; i++) { \
        int idx = tid + i * 128; \
        int px = idx >> 3, c4 = (idx & 7) << 2; \
        *reinterpret_cast<uint2*>(&sAh[(s)*OAT + px*40 + c4]) = hv[i]; \
        *reinterpret_cast<uint2*>(&sAl[(s)*OAT + px*40 + c4]) = lv[i]; \
    } \
} while (0)
#define OM_CPB(kc, s) do { \
    _Pragma("unroll") \
    for (int i = 0; i < 2; i++) { \
        int e = tid + i * 128; \
        int r = e >> 2, cs = (e & 3) * 8; \
        size_t gb = (size_t)(col0 + r) * NF + ((kc) << 5) + cs; \
        cp16(smem_u32(&sBh[(s)*OBT + r*40 + cs]), g_cwh + gb); \
        cp16(smem_u32(&sBl[(s)*OBT + r*40 + cs]), g_cwl + gb); \
    } \
} while (0)

    const int NK = NF / 32;
    uint2 hv[4], lv[4];
    om_gather(0, b, h, tid, hv, lv);
    OM_STS(0);
    OM_CPB(0, 0);
    CP_COMMIT();
    om_gather(1, b, h, tid, hv, lv);

    for (int kc = 0; kc < NK; kc++) {
        int cur = kc & 1;
        CP_WAIT0();
        __syncthreads();
        if (kc + 1 < NK) {
            OM_STS(cur ^ 1);
            OM_CPB(kc + 1, cur ^ 1);
            CP_COMMIT();
        }
        if (kc + 2 < NK)
            om_gather(kc + 2, b, h, tid, hv, lv);

#pragma unroll
        for (int ks = 0; ks < 2; ks++) {
            uint32_t aH[2][4], aL[2][4], bH[4][2], bL[4][2];
#pragma unroll
            for (int mi = 0; mi < 2; mi++) {
                int rowa = wm * 32 + mi * 16 + (lane & 15);
                int cola = ks * 16 + (lane >> 4) * 8;
                LDSM_X4(aH[mi], smem_u32(&sAh[cur*OAT + rowa*40 + cola]));
                LDSM_X4(aL[mi], smem_u32(&sAl[cur*OAT + rowa*40 + cola]));
            }
#pragma unroll
            for (int jp = 0; jp < 2; jp++) {
                int rowb = wn * 32 + jp * 16 + ((lane >> 4) & 1) * 8 + (lane & 7);
                int colb = ks * 16 + ((lane >> 3) & 1) * 8;
                uint32_t t4[4];
                LDSM_X4(t4, smem_u32(&sBh[cur*OBT + rowb*40 + colb]));
                bH[jp*2][0] = t4[0]; bH[jp*2][1] = t4[1];
                bH[jp*2+1][0] = t4[2]; bH[jp*2+1][1] = t4[3];
                LDSM_X4(t4, smem_u32(&sBl[cur*OBT + rowb*40 + colb]));
                bL[jp*2][0] = t4[0]; bL[jp*2][1] = t4[1];
                bL[jp*2+1][0] = t4[2]; bL[jp*2+1][1] = t4[3];
            }
#pragma unroll
            for (int mi = 0; mi < 2; mi++)
#pragma unroll
                for (int j = 0; j < 4; j++) {
                    MMA16816(acc[mi][j], aH[mi], bH[j]);
                    MMA16816(acc[mi][j], aH[mi], bL[j]);
                    MMA16816(acc[mi][j], aL[mi], bH[j]);
                }
        }
    }
#undef OM_STS
#undef OM_CPB

    int g = lane >> 2, t = lane & 3;
#pragma unroll
    for (int mi = 0; mi < 2; mi++)
#pragma unroll
        for (int j = 0; j < 4; j++) {
            int col = col0 + wn * 32 + j * 8 + t * 2;
            float2 bv = *reinterpret_cast<const float2*>(&g_combB[col]);
            int r0 = row0 + wm * 32 + mi * 16 + g;
            float2 o0 = make_float2(acc[mi][j][0] + bv.x, acc[mi][j][1] + bv.y);
            float2 o1 = make_float2(acc[mi][j][2] + bv.x, acc[mi][j][3] + bv.y);
            *reinterpret_cast<float2*>(&g_offmask[(size_t)r0 * NOP + col]) = o0;
            *reinterpret_cast<float2*>(&g_offmask[(size_t)(r0 + 8) * NOP + col]) = o1;
        }
}

// ------- merged prep -------
__global__ void __launch_bounds__(256) allprep_kernel(
    const float* __restrict__ x, const float* __restrict__ qkv_w,
    const float* __restrict__ proj_w,
    const float* __restrict__ off_pconv_w, const float* __restrict__ off_w,
    const float* __restrict__ off_b, const float* __restrict__ mask_pconv_w,
    const float* __restrict__ mask_w, const float* __restrict__ mask_b)
{
    int bid = blockIdx.x, tid = threadIdx.x;
    if (bid < NOP * 3) {
        int o = bid / 3;
        int f = (bid % 3) * 256 + tid;
        if (o >= 153) {
            g_cwh[(size_t)o * NF + f] = __float2half_rn(0.f);
            g_cwl[(size_t)o * NF + f] = __float2half_rn(0.f);
            if (tid == 0 && (bid % 3) == 0) g_combB[o] = 0.f;
            return;
        }
        bool is_mask = (o >= 144);
        int g = 0, j = 0, kk = 0;
        if (!is_mask) { g = o / 18; j = o % 18; } else { kk = o - 144; }
        float s;
        if (f < 576) {
            int t = f >> 6, ic = f & 63;
            s = 0.f;
            if (!is_mask) {
                const float* ow = off_w + (g * 18 + j) * 256;
                const float* pc = off_pconv_w + ((size_t)(g * 64) * 64 + ic) * 9 + t;
#pragma unroll 4
                for (int oc = 0; oc < 64; oc++) s += ow[oc] * pc[(size_t)oc * 64 * 9];
            } else {
                const float* mw = mask_w + kk * 256;
                const float* pc = mask_pconv_w + (size_t)ic * 9 + t;
#pragma unroll 4
                for (int oc = 0; oc < 64; oc++) s += mw[oc] * pc[(size_t)oc * 64 * 9];
            }
        } else {
            int ch = f - 512;
            s = is_mask ? mask_w[kk * 256 + ch] : off_w[(g * 18 + j) * 256 + ch];
        }
        __half h, l; split1(s, h, l);
        g_cwh[(size_t)o * NF + f] = h;
        g_cwl[(size_t)o * NF + f] = l;
        if (tid == 0 && (bid % 3) == 0)
            g_combB[o] = is_mask ? mask_b[kk]
                                 : (off_b[g * 18 + j] + c_PTS[j] * (float)(2 * g + 1));
    } else if (bid < NOP * 3 + C3 + CD) {
        int wb = bid - NOP * 3;
        if (wb < C3) {
            __half h, l; split1(qkv_w[(size_t)tid * C3 + wb], h, l);
            g_qwh[(size_t)wb * CD + tid] = h;
            g_qwl[(size_t)wb * CD + tid] = l;
        } else {
            int o = wb - C3;
            __half h, l; split1(proj_w[(size_t)tid * CD + o], h, l);
            g_pwh[(size_t)o * CD + tid] = h;
            g_pwl[(size_t)o * CD + tid] = l;
        }
    } else {
        int xb = bid - (NOP * 3 + C3 + CD);
        int i = (xb * 256 + tid) * 4;
        float4 v = *reinterpret_cast<const float4*>(&x[i]);
        float f[4] = {v.x, v.y, v.z, v.w};
#pragma unroll
        for (int j = 0; j < 4; j++) {
            __half h, l; split1(f[j], h, l);
            g_xhi[i + j] = h; g_xlo[i + j] = l;
        }
    }
}

// ---------------- depthwise 3x3 ----------------
__global__ void __launch_bounds__(192) dwconv_kernel(
    const float* __restrict__ in, const float* __restrict__ w,
    const float* __restrict__ bias)
{
    int c = threadIdx.x * 4;
    int x0 = blockIdx.x * 4, y = blockIdx.y, b = blockIdx.z;
    float4 bz = *reinterpret_cast<const float4*>(&bias[c]);
    float4 acc[4] = {bz, bz, bz, bz};
#pragma unroll
    for (int ky = 0; ky < 3; ky++) {
        int yy = y + ky - 1;
        if (yy < 0 || yy >= HD) continue;
        const float* rowp = in + ((size_t)(b * HD + yy) * WD) * C3 + c;
        float4 iv[6];
#pragma unroll
        for (int j = 0; j < 6; j++) {
            int xx = x0 - 1 + j;
            iv[j] = (xx >= 0 && xx < WD)
                ? *reinterpret_cast<const float4*>(rowp + (size_t)xx * C3)
                : make_float4(0.f, 0.f, 0.f, 0.f);
        }
#pragma unroll
        for (int kx = 0; kx < 3; kx++) {
            float4 wv = *reinterpret_cast<const float4*>(&w[(ky * 3 + kx) * C3 + c]);
#pragma unroll
            for (int p = 0; p < 4; p++) {
                acc[p].x += wv.x * iv[p + kx].x; acc[p].y += wv.y * iv[p + kx].y;
                acc[p].z += wv.z * iv[p + kx].z; acc[p].w += wv.w * iv[p + kx].w;
            }
        }
    }
#pragma unroll
    for (int p = 0; p < 4; p++) {
        size_t pix = (size_t)(b * HD + y) * WD + x0 + p;
        if (c < CD) {
            __half h0,h1,h2,h3,l0,l1,l2,l3;
            split1(acc[p].x,h0,l0); split1(acc[p].y,h1,l1);
            split1(acc[p].z,h2,l2); split1(acc[p].w,h3,l3);
            size_t o = pix * CD + c;
            *reinterpret_cast<__half2*>(&g_qh[o])   = __halves2half2(h0,h1);
            *reinterpret_cast<__half2*>(&g_qh[o+2]) = __halves2half2(h2,h3);
            *reinterpret_cast<__half2*>(&g_ql[o])   = __halves2half2(l0,l1);
            *reinterpret_cast<__half2*>(&g_ql[o+2]) = __halves2half2(l2,l3);
        } else if (c < 2 * CD) {
            float2* bp = &g_kv[pix * CD + (c - CD)];
            bp[0].x = acc[p].x; bp[1].x = acc[p].y;
            bp[2].x = acc[p].z; bp[3].x = acc[p].w;
        } else {
            float2* bp = &g_kv[pix * CD + (c - 2 * CD)];
            bp[0].y = acc[p].x; bp[1].y = acc[p].y;
            bp[2].y = acc[p].z; bp[3].y = acc[p].w;
        }
    }
}

// ------- deformable attention: batched loads + stage-major reduction -------
__global__ void __launch_bounds__(256) attn_kernel()
{
    int warp = threadIdx.x >> 5, lane = threadIdx.x & 31;
    int px = blockIdx.x * 8 + warp;
    int g = blockIdx.y, b = blockIdx.z;
    int h = px >> 6, w = px & 63;

    size_t pix = (size_t)(b * HD + h) * WD + w;
    const float* om = g_offmask + pix * NOP;
    // lane-parallel om fetch: 2 coalesced loads instead of 28 uniform scalars
    float v1 = (lane < 18) ? om[g * 18 + lane] : 0.f;
    float v2 = (lane < 9)  ? om[144 + lane]    : 0.f;

    size_t qi = pix * CD + g * HCD + lane;
    float qv = (__half2float(g_qh[qi]) + __half2float(g_ql[qi]))
             * 0.17677669529663687f;

    float attn[KP], vk[KP];
    // phase 1: independent per-tap gathers + per-lane partial dots
#pragma unroll
    for (int k = 0; k < KP; k++) {
        float ox = __shfl_sync(0xffffffffu, v1, 2 * k);
        float oy = __shfl_sync(0xffffffffu, v1, 2 * k + 1);
        float mk = __shfl_sync(0xffffffffu, v2, k);
        float cx = fminf(fmaxf((float)w + ox, 0.f), (float)(WD - 1));
        float cy = fminf(fmaxf((float)h + oy, 0.f), (float)(HD - 1));
        float x0f = floorf(cx), y0f = floorf(cy);
        float fx = cx - x0f, fy = cy - y0f;
        int x0 = (int)x0f, y0 = (int)y0f;
        int x1 = min(x0 + 1, WD - 1), y1 = min(y0 + 1, HD - 1);
        size_t i00 = ((size_t)(b * HD + y0) * WD + x0) * CD + g * HCD + lane;
        size_t i01 = ((size_t)(b * HD + y0) * WD + x1) * CD + g * HCD + lane;
        size_t i10 = ((size_t)(b * HD + y1) * WD + x0) * CD + g * HCD + lane;
        size_t i11 = ((size_t)(b * HD + y1) * WD + x1) * CD + g * HCD + lane;
        float2 kv00 = g_kv[i00], kv01 = g_kv[i01];
        float2 kv10 = g_kv[i10], kv11 = g_kv[i11];
        float w00 = (1.f - fx) * (1.f - fy), w01 = fx * (1.f - fy);
        float w10 = (1.f - fx) * fy,         w11 = fx * fy;
        float kvv = kv00.x*w00 + kv01.x*w01 + kv10.x*w10 + kv11.x*w11;
        float vvv = kv00.y*w00 + kv01.y*w01 + kv10.y*w10 + kv11.y*w11;
        attn[k] = qv * (kvv * mk);      // per-lane partial (not yet reduced)
        vk[k]   = vvv * mk;
    }
    // phase 2: stage-major butterfly — 9 independent chains interleaved
#pragma unroll
    for (int s = 16; s; s >>= 1) {
#pragma unroll
        for (int k = 0; k < KP; k++)
            attn[k] += __shfl_xor_sync(0xffffffffu, attn[k], s);
    }
    float m = attn[0];
#pragma unroll
    for (int k = 1; k < KP; k++) m = fmaxf(m, attn[k]);
    float ssum = 0.f, o = 0.f;
#pragma unroll
    for (int k = 0; k < KP; k++) {
        float e = __expf(attn[k] - m);
        ssum += e;
        o += e * vk[k];
    }
    o /= ssum;
    size_t oi = pix * CD + g * HCD + lane;
    __half hh, ll; split1(o, hh, ll);
    g_aoh[oi] = hh; g_aol[oi] = ll;
}

// --------------------------------- launch ---------------------------------
extern "C" void kernel_launch(void* const* d_in, const int* in_sizes, int n_in,
                              void* d_out, int out_size)
{
    const float* x            = (const float*)d_in[0];
    const float* qkv_w        = (const float*)d_in[1];
    const float* qkv_b        = (const float*)d_in[2];
    const float* dw_w         = (const float*)d_in[3];
    const float* dw_b         = (const float*)d_in[4];
    const float* off_pconv_w  = (const float*)d_in[5];
    const float* off_w        = (const float*)d_in[6];
    const float* off_b        = (const float*)d_in[7];
    const float* mask_pconv_w = (const float*)d_in[8];
    const float* mask_w       = (const float*)d_in[9];
    const float* mask_b       = (const float*)d_in[10];
    const float* proj_w       = (const float*)d_in[11];
    const float* proj_b       = (const float*)d_in[12];
    float* out = (float*)d_out;

    cudaFuncSetAttribute(gemm_kernel,
                         cudaFuncAttributeMaxDynamicSharedMemorySize, GEMM_SMEM);
    cudaFuncSetAttribute(offmask_gemm_kernel,
                         cudaFuncAttributeMaxDynamicSharedMemorySize, OM_SMEM);

    __half *xh, *xl, *qwh, *qwl, *pwh, *pwl, *aoh, *aol;
    float *qkv;
    cudaGetSymbolAddress((void**)&xh, g_xhi);   cudaGetSymbolAddress((void**)&xl, g_xlo);
    cudaGetSymbolAddress((void**)&qwh, g_qwh);  cudaGetSymbolAddress((void**)&qwl, g_qwl);
    cudaGetSymbolAddress((void**)&pwh, g_pwh);  cudaGetSymbolAddress((void**)&pwl, g_pwl);
    cudaGetSymbolAddress((void**)&aoh, g_aoh);  cudaGetSymbolAddress((void**)&aol, g_aol);
    cudaGetSymbolAddress((void**)&qkv, g_qkv);

    allprep_kernel<<<NOP * 3 + C3 + CD + 2048, 256>>>(
        x, qkv_w, proj_w, off_pconv_w, off_w, off_b,
        mask_pconv_w, mask_w, mask_b);
    {
        dim3 grid(C3 / 64, MR / 128);
        gemm_kernel<<<grid, 256, GEMM_SMEM>>>(xh, xl, qwh, qwl, qkv_b, qkv,
                                              C3, CD, CD);
    }
    {
        dim3 grid(WD / 4, HD, BD);
        dwconv_kernel<<<grid, 192>>>(qkv, dw_w, dw_b);
    }
    {
        dim3 grid(NOP / 64, MR / 64);
        offmask_gemm_kernel<<<grid, 128, OM_SMEM>>>();     // profiled slot
    }
    {
        dim3 grid(PD / 8, GD, BD);
        attn_kernel<<<grid, 256>>>();
    }
    {
        dim3 grid(CD / 64, MR / 128);
        gemm_kernel<<<grid, 256, GEMM_SMEM>>>(aoh, aol, pwh, pwl, proj_b, out,
                                              CD, CD, 0);
    }
}